// round 16
// baseline (speedup 1.0000x reference)
#include <cuda_runtime.h>
#include <cuda_bf16.h>
#include <mma.h>
#include <cstdint>

using namespace nvcuda;

// Problem constants
#define BATCH   2
#define LSEQ    4096
#define DIMSZ   512
#define NHEADS  8
#define HD      64
#define KSZ     33
#define MROWS   (BATCH * LSEQ)        // 8192
#define QKVDIM  (3 * DIMSZ)           // 1536
#define KIN     512
#define K2      1024                  // [hi|lo] compact layout
#define BQ      128

// GEMM tiling: CTA 128x256, 16 warps (4x4), warp tile 32x64
#define MT      128
#define NT      256
#define KC      64
#define NIT     (KIN / KC)            // 8
#define SRD     72
#define AT_B    (128 * SRD * 2)       // 18432
#define BT_B    (256 * SRD * 2)       // 36864
#define STAGE_BYTES (2 * AT_B + 2 * BT_B)   // 110592
#define SM_TOTAL (2 * STAGE_BYTES)          // 221184

// Attention
#define KVP     66
#define ATT_SMEM (2 * 160 * KVP * 4)  // 84480

// Scratch (device globals; allocation is forbidden)
__device__ float          g_qkv[(size_t)MROWS * QKVDIM];
__device__ __nv_bfloat16  g_a2 [(size_t)MROWS * K2];     // [hi|lo]
__device__ __nv_bfloat16  g_wq2[(size_t)QKVDIM * K2];
__device__ __nv_bfloat16  g_wp2[(size_t)DIMSZ * K2];

typedef unsigned long long ull;

__device__ __forceinline__ uint32_t cvta_smem(const void* p) {
    uint32_t a;
    asm("{ .reg .u64 t; cvta.to.shared.u64 t, %1; cvt.u32.u64 %0, t; }"
        : "=r"(a) : "l"(p));
    return a;
}

// Packed fp32x2 ops (Blackwell FFMA2 path)
__device__ __forceinline__ ull pk2(float x, float y) {
    ull r; asm("mov.b64 %0, {%1, %2};" : "=l"(r) : "f"(x), "f"(y)); return r;
}
__device__ __forceinline__ void upk2(ull v, float& x, float& y) {
    asm("mov.b64 {%0, %1}, %2;" : "=f"(x), "=f"(y) : "l"(v));
}
__device__ __forceinline__ ull ffma2(ull a, ull b, ull c) {
    ull d; asm("fma.rn.f32x2 %0, %1, %2, %3;" : "=l"(d) : "l"(a), "l"(b), "l"(c));
    return d;
}

// ---------------------------------------------------------------------------
// Merged fp32 -> compact split-bf16 for all three operands in one launch.
// ---------------------------------------------------------------------------
__global__ void __launch_bounds__(256) split_bf16_all(
    const float4* __restrict__ inx,  __nv_bfloat16* __restrict__ outx,
    const float4* __restrict__ inq,  __nv_bfloat16* __restrict__ outq,
    const float4* __restrict__ inp,  __nv_bfloat16* __restrict__ outp)
{
    const float4* in;
    __nv_bfloat16* out;
    int base;
    int bid = blockIdx.x;
    if (bid < 4096)      { in = inx; out = outx; base = bid; }
    else if (bid < 4864) { in = inq; out = outq; base = bid - 4096; }
    else                 { in = inp; out = outp; base = bid - 4864; }

    int i = base * 256 + threadIdx.x;
    int row = i >> 7;
    int k   = (i & 127) * 4;
    float4 x = in[i];
    __nv_bfloat16 h0 = __float2bfloat16(x.x), h1 = __float2bfloat16(x.y);
    __nv_bfloat16 h2 = __float2bfloat16(x.z), h3 = __float2bfloat16(x.w);
    __nv_bfloat16 l0 = __float2bfloat16(x.x - __bfloat162float(h0));
    __nv_bfloat16 l1 = __float2bfloat16(x.y - __bfloat162float(h1));
    __nv_bfloat16 l2 = __float2bfloat16(x.z - __bfloat162float(h2));
    __nv_bfloat16 l3 = __float2bfloat16(x.w - __bfloat162float(h3));
    __nv_bfloat16* bp = out + (size_t)row * K2;
    __nv_bfloat162* ph = (__nv_bfloat162*)(bp + k);
    __nv_bfloat162* pl = (__nv_bfloat162*)(bp + KIN + k);
    ph[0] = {h0, h1}; ph[1] = {h2, h3};
    pl[0] = {l0, l1}; pl[1] = {l2, l3};
}

// ---------------------------------------------------------------------------
// wmma GEMM with 3-term split accumulation (frozen — at legacy HMMA plateau)
// ---------------------------------------------------------------------------
__global__ void __launch_bounds__(512, 1) gemm_wmma(
    const __nv_bfloat16* __restrict__ A, const __nv_bfloat16* __restrict__ B,
    const float* __restrict__ bias, float* __restrict__ C, int N)
{
    extern __shared__ char sh[];
    const uint32_t sbase = cvta_smem(sh);

    const int tid  = threadIdx.x;
    const int wid  = tid >> 5;
    const int wm   = wid >> 2;
    const int wn   = wid & 3;
    const int m0 = blockIdx.y * MT;
    const int n0 = blockIdx.x * NT;

    const __nv_bfloat16* Ag = A + (size_t)m0 * K2;
    const __nv_bfloat16* Bg = B + (size_t)n0 * K2;

    float* bias_t = (float*)sh;
    for (int idx = tid; idx < 16 * NT; idx += 512)
        bias_t[idx] = bias[n0 + (idx & (NT - 1))];
    __syncthreads();

    wmma::fragment<wmma::accumulator, 16, 16, 16, float> acc[2][4];
#pragma unroll
    for (int i = 0; i < 2; i++)
#pragma unroll
        for (int j = 0; j < 4; j++)
            wmma::load_matrix_sync(acc[i][j],
                                   bias_t + wn * 64 + j * 16, NT,
                                   wmma::mem_row_major);
    __syncthreads();

    auto load_stage = [&](int stage, int it) {
        const int kc = it * KC;
        const uint32_t s0 = sbase + stage * STAGE_BYTES;
#pragma unroll
        for (int t = 0; t < 4; t++) {
            int idx = tid + t * 512;
            int half = idx >> 10;
            int row  = (idx >> 3) & 127;
            int c16  = idx & 7;
            uint32_t dst = s0 + half * AT_B + row * (SRD * 2) + c16 * 16;
            const void* src = Ag + (size_t)row * K2 + half * KIN + kc + c16 * 8;
            asm volatile("cp.async.cg.shared.global [%0], [%1], 16;"
                         :: "r"(dst), "l"(src));
        }
#pragma unroll
        for (int t = 0; t < 8; t++) {
            int idx = tid + t * 512;
            int half = idx >> 11;
            int row  = (idx >> 3) & 255;
            int c16  = idx & 7;
            uint32_t dst = s0 + 2 * AT_B + half * BT_B + row * (SRD * 2) + c16 * 16;
            const void* src = Bg + (size_t)row * K2 + half * KIN + kc + c16 * 8;
            asm volatile("cp.async.cg.shared.global [%0], [%1], 16;"
                         :: "r"(dst), "l"(src));
        }
    };

    load_stage(0, 0);
    asm volatile("cp.async.commit_group;" ::: "memory");
    load_stage(1, 1);
    asm volatile("cp.async.commit_group;" ::: "memory");

    for (int it = 0; it < NIT; it++) {
        if (it + 1 < NIT)
            asm volatile("cp.async.wait_group 1;" ::: "memory");
        else
            asm volatile("cp.async.wait_group 0;" ::: "memory");
        __syncthreads();

        const char* stg = sh + (it & 1) * STAGE_BYTES;
        const __nv_bfloat16* Ahi = (const __nv_bfloat16*)stg;
        const __nv_bfloat16* Alo = (const __nv_bfloat16*)(stg + AT_B);
        const __nv_bfloat16* Bhi = (const __nv_bfloat16*)(stg + 2 * AT_B);
        const __nv_bfloat16* Blo = (const __nv_bfloat16*)(stg + 2 * AT_B + BT_B);

#pragma unroll
        for (int ks = 0; ks < 4; ks++) {
            wmma::fragment<wmma::matrix_a, 16, 16, 16, __nv_bfloat16,
                           wmma::row_major> af[2];
            wmma::fragment<wmma::matrix_b, 16, 16, 16, __nv_bfloat16,
                           wmma::col_major> bfh[4], bfl[4];
#pragma unroll
            for (int i = 0; i < 2; i++)
                wmma::load_matrix_sync(af[i],
                    Ahi + (size_t)(wm * 32 + i * 16) * SRD + ks * 16, SRD);
#pragma unroll
            for (int j = 0; j < 4; j++)
                wmma::load_matrix_sync(bfh[j],
                    Bhi + (size_t)(wn * 64 + j * 16) * SRD + ks * 16, SRD);
#pragma unroll
            for (int i = 0; i < 2; i++)
#pragma unroll
                for (int j = 0; j < 4; j++)
                    wmma::mma_sync(acc[i][j], af[i], bfh[j], acc[i][j]);
#pragma unroll
            for (int j = 0; j < 4; j++)
                wmma::load_matrix_sync(bfl[j],
                    Blo + (size_t)(wn * 64 + j * 16) * SRD + ks * 16, SRD);
#pragma unroll
            for (int i = 0; i < 2; i++)
#pragma unroll
                for (int j = 0; j < 4; j++)
                    wmma::mma_sync(acc[i][j], af[i], bfl[j], acc[i][j]);
#pragma unroll
            for (int i = 0; i < 2; i++)
                wmma::load_matrix_sync(af[i],
                    Alo + (size_t)(wm * 32 + i * 16) * SRD + ks * 16, SRD);
#pragma unroll
            for (int i = 0; i < 2; i++)
#pragma unroll
                for (int j = 0; j < 4; j++)
                    wmma::mma_sync(acc[i][j], af[i], bfh[j], acc[i][j]);
        }
        __syncthreads();

        const int nx = it + 2;
        if (nx < NIT) {
            load_stage(nx & 1, nx);
            asm volatile("cp.async.commit_group;" ::: "memory");
        }
    }

#pragma unroll
    for (int i = 0; i < 2; i++)
#pragma unroll
        for (int j = 0; j < 4; j++)
            wmma::store_matrix_sync(
                C + (size_t)(m0 + wm * 32 + i * 16) * N + n0 + wn * 64 + j * 16,
                acc[i][j], N, wmma::mem_row_major);
}

// ---------------------------------------------------------------------------
// Neighborhood attention, 4 QUERIES PER THREAD (8 threads per query-quad,
// dp = 8 floats). Each K/V row LDS feeds 4 queries -> smem traffic halved
// again vs 2q/thread. Union window <= 36 rows, d_i in {0..3}; inactive rows
// masked to -1e30. FFMA2 math, dedup exp, fused split-bf16 epilogue.
// ---------------------------------------------------------------------------
__global__ void __launch_bounds__(256) na1d_kernel(
    const float* __restrict__ qkv, __nv_bfloat16* __restrict__ out2)
{
    extern __shared__ float shf[];
    float* Ks = shf;                  // [160][KVP]
    float* Vs = shf + 160 * KVP;

    const int tid = threadIdx.x;
    const int b  = blockIdx.z;
    const int h  = blockIdx.y;
    const int q0 = blockIdx.x * BQ;

    const int smin = min(max(q0 - (KSZ / 2), 0), LSEQ - KSZ);
    const int smax = min(max(q0 + BQ - 1 - (KSZ / 2), 0), LSEQ - KSZ);
    const int nk   = smax - smin + KSZ;   // <= 160
    const int lim  = nk * 16;             // 16B units per operand (<= 2560)

    // Batched staging: 2 rounds of 5 predicated LDG.128 per operand
    const float* kb = qkv + ((size_t)(b * LSEQ + smin)) * QKVDIM + DIMSZ + h * HD;
#pragma unroll
    for (int r = 0; r < 2; r++) {
        uint4 kreg[5], vreg[5];
#pragma unroll
        for (int i = 0; i < 5; i++) {
            int idx = tid + (r * 5 + i) * 256;
            if (idx < lim) {
                int row = idx >> 4, c = (idx & 15) * 4;
                kreg[i] = *(const uint4*)(kb + (size_t)row * QKVDIM + c);
                vreg[i] = *(const uint4*)(kb + (size_t)row * QKVDIM + DIMSZ + c);
            }
        }
#pragma unroll
        for (int i = 0; i < 5; i++) {
            int idx = tid + (r * 5 + i) * 256;
            if (idx < lim) {
                int row = idx >> 4, c = (idx & 15) * 4;
                ull* kd = (ull*)(Ks + row * KVP + c);
                kd[0] = ((ull)kreg[i].y << 32) | kreg[i].x;
                kd[1] = ((ull)kreg[i].w << 32) | kreg[i].z;
                ull* vd = (ull*)(Vs + row * KVP + c);
                vd[0] = ((ull)vreg[i].y << 32) | vreg[i].x;
                vd[1] = ((ull)vreg[i].w << 32) | vreg[i].z;
            }
        }
    }
    __syncthreads();

    const int lane = tid & 31;
    const int t8   = tid & 7;             // position within 8-thread group
    const int quad = tid >> 3;            // query-quad index (0..31)
    const int l0   = q0 + 4 * quad;
    const int dp   = t8 * 8;              // this thread's 8-dim slice

    const int st0 = min(max(l0 - (KSZ / 2), 0), LSEQ - KSZ);
    const int base = st0 - smin;
    int d[4];
#pragma unroll
    for (int i = 0; i < 4; i++)
        d[i] = min(max(l0 + i - (KSZ / 2), 0), LSEQ - KSZ) - st0;   // 0..3

    // q slices for 4 queries: 4 ull (8 floats) each, scaled
    ull q2[4][4];
#pragma unroll
    for (int i = 0; i < 4; i++) {
        const float* qp = qkv + ((size_t)(b * LSEQ + l0 + i)) * QKVDIM + h * HD + dp;
        float4 v0 = *(const float4*)(qp);
        float4 v1 = *(const float4*)(qp + 4);
        q2[i][0] = pk2(v0.x * 0.125f, v0.y * 0.125f);
        q2[i][1] = pk2(v0.z * 0.125f, v0.w * 0.125f);
        q2[i][2] = pk2(v1.x * 0.125f, v1.y * 0.125f);
        q2[i][3] = pk2(v1.z * 0.125f, v1.w * 0.125f);
    }

    // Score loop over union rows (36 iters); keep only owned scores
    float own[4][5];
    float mx[4] = {-1e30f, -1e30f, -1e30f, -1e30f};
#pragma unroll
    for (int jj = 0; jj < 36; jj++) {
        int row = min(base + jj, nk - 1);
        const ull* kr2 = (const ull*)(Ks + row * KVP + dp);
        ull a[4] = {0ULL, 0ULL, 0ULL, 0ULL};
#pragma unroll
        for (int s = 0; s < 4; s++) {
            ull kv = kr2[s];
#pragma unroll
            for (int i = 0; i < 4; i++)
                a[i] = ffma2(q2[i][s], kv, a[i]);
        }
#pragma unroll
        for (int i = 0; i < 4; i++) {
            float x, y;
            upk2(a[i], x, y);
            float p = x + y;
            p += __shfl_xor_sync(0xFFFFFFFF, p, 1);
            p += __shfl_xor_sync(0xFFFFFFFF, p, 2);
            p += __shfl_xor_sync(0xFFFFFFFF, p, 4);
            bool act = (jj >= d[i]) && (jj <= d[i] + 32);
            if (!act) p = -1e30f;
            mx[i] = fmaxf(mx[i], p);
            if ((jj & 7) == t8) own[i][jj >> 3] = p;
        }
    }

    // Dedup exp over owned slots; partial sums reduced over the 8-group
    float sum[4] = {0.0f, 0.0f, 0.0f, 0.0f};
#pragma unroll
    for (int slot = 0; slot < 5; slot++) {
        int jj = slot * 8 + t8;
#pragma unroll
        for (int i = 0; i < 4; i++) {
            float e = 0.0f;
            if (jj < 36) e = __expf(own[i][slot] - mx[i]);
            own[i][slot] = e;
            sum[i] += e;
        }
    }
    float inv[4];
#pragma unroll
    for (int i = 0; i < 4; i++) {
        float s = sum[i];
        s += __shfl_xor_sync(0xFFFFFFFF, s, 1);
        s += __shfl_xor_sync(0xFFFFFFFF, s, 2);
        s += __shfl_xor_sync(0xFFFFFFFF, s, 4);
        inv[i] = 1.0f / s;
    }

    // PV loop: V row loaded once, used for all 4 queries
    ull o2[4][4];
#pragma unroll
    for (int i = 0; i < 4; i++)
#pragma unroll
        for (int s = 0; s < 4; s++) o2[i][s] = 0ULL;
#pragma unroll
    for (int jj = 0; jj < 36; jj++) {
        int row = min(base + jj, nk - 1);
        int src = (lane & ~7) | (jj & 7);
        ull p2[4];
#pragma unroll
        for (int i = 0; i < 4; i++) {
            float p = __shfl_sync(0xFFFFFFFF, own[i][jj >> 3], src);
            p2[i] = pk2(p, p);
        }
        const ull* vr2 = (const ull*)(Vs + row * KVP + dp);
#pragma unroll
        for (int s = 0; s < 4; s++) {
            ull vv = vr2[s];
#pragma unroll
            for (int i = 0; i < 4; i++)
                o2[i][s] = ffma2(p2[i], vv, o2[i][s]);
        }
    }

    // Fused split epilogue for all 4 queries (8 floats each)
#pragma unroll
    for (int i = 0; i < 4; i++) {
        __nv_bfloat16* orow = out2 + (size_t)(b * LSEQ + l0 + i) * K2 + h * HD + dp;
        __nv_bfloat162* ph = (__nv_bfloat162*)orow;
        __nv_bfloat162* pl = (__nv_bfloat162*)(orow + KIN);
#pragma unroll
        for (int s = 0; s < 4; s++) {
            float x, y;
            upk2(o2[i][s], x, y);
            x *= inv[i]; y *= inv[i];
            __nv_bfloat16 hx = __float2bfloat16(x);
            __nv_bfloat16 hy = __float2bfloat16(y);
            __nv_bfloat16 lx = __float2bfloat16(x - __bfloat162float(hx));
            __nv_bfloat16 ly = __float2bfloat16(y - __bfloat162float(hy));
            ph[s] = {hx, hy};
            pl[s] = {lx, ly};
        }
    }
}

// ---------------------------------------------------------------------------
// Launch
// ---------------------------------------------------------------------------
extern "C" void kernel_launch(void* const* d_in, const int* in_sizes, int n_in,
                              void* d_out, int out_size)
{
    const float* x      = (const float*)d_in[0];
    const float* w_qkv  = (const float*)d_in[1];
    const float* b_qkv  = (const float*)d_in[2];
    const float* w_proj = (const float*)d_in[3];
    const float* b_proj = (const float*)d_in[4];
    float*       out    = (float*)d_out;

    float* qkv;
    __nv_bfloat16 *a2, *wq2, *wp2;
    cudaGetSymbolAddress((void**)&qkv, g_qkv);
    cudaGetSymbolAddress((void**)&a2,  g_a2);
    cudaGetSymbolAddress((void**)&wq2, g_wq2);
    cudaGetSymbolAddress((void**)&wp2, g_wp2);

    cudaFuncSetAttribute(na1d_kernel,
                         cudaFuncAttributeMaxDynamicSharedMemorySize, ATT_SMEM);
    cudaFuncSetAttribute(gemm_wmma,
                         cudaFuncAttributeMaxDynamicSharedMemorySize, SM_TOTAL);

    // All three [hi|lo] splits in one launch
    split_bf16_all<<<5120, 256>>>((const float4*)x, a2,
                                  (const float4*)w_qkv, wq2,
                                  (const float4*)w_proj, wp2);

    // 1) QKV projection
    dim3 g1(QKVDIM / NT, MROWS / MT);
    gemm_wmma<<<g1, 512, SM_TOTAL>>>(a2, wq2, b_qkv, qkv, QKVDIM);

    // 2) Neighborhood attention (4 queries/thread, writes split operand)
    dim3 g2(LSEQ / BQ, NHEADS, BATCH);
    na1d_kernel<<<g2, 256, ATT_SMEM>>>(qkv, a2);

    // 3) Output projection
    dim3 g3(DIMSZ / NT, MROWS / MT);
    gemm_wmma<<<g3, 512, SM_TOTAL>>>(a2, wp2, b_proj, out, DIMSZ);
}